// round 2
// baseline (speedup 1.0000x reference)
#include <cuda_runtime.h>
#include <cstdint>

// out = relu( mask_row ? (features + residuals[0] + residuals[1]) : 0 )
// features:  (256, 128, 1024) f32
// residuals: (2, 256, 128, 1024) f32
// mol_slice: (256, 2) int64 OR int32 (JAX x64-dependent) — detected at runtime
//
// One block per (b, a) row. 256 threads * float4 = 1024 floats/row.
// Masked rows issue zero loads — only a 128B-per-thread zero store.

#define BATCH 256
#define MAX_ATOM 128
#define N_FEAT 1024
#define THREADS 256   // N_FEAT/4

__global__ __launch_bounds__(THREADS)
void dense_block_end_kernel(const float* __restrict__ features,
                            const float* __restrict__ residuals,
                            const void*  __restrict__ mol_slice,
                            float* __restrict__ out)
{
    const int row = blockIdx.x;            // 0 .. BATCH*MAX_ATOM-1
    const int b   = row >> 7;              // / MAX_ATOM
    const int a   = row & (MAX_ATOM - 1);  // % MAX_ATOM

    // Runtime dtype sniff for mol_slice:
    //   int32 layout: [M0, 1024, M1, 1024, ...]  -> word[1] == 1024
    //   int64 layout: [M0, 0, 1024, 0, ...]      -> word[1] == 0 (hi word, M<=128)
    const int* ms32 = (const int*)mol_slice;
    int n_atoms;
    if (ms32[1] == N_FEAT) {
        n_atoms = ms32[2 * b];
    } else {
        n_atoms = (int)((const long long*)mol_slice)[2 * b];
    }

    const size_t base = (size_t)row * N_FEAT + threadIdx.x * 4;
    float4* o = (float4*)(out + base);

    if (a >= n_atoms) {
        *o = make_float4(0.f, 0.f, 0.f, 0.f);
        return;
    }

    const size_t res_stride = (size_t)BATCH * MAX_ATOM * N_FEAT;
    float4 f  = *(const float4*)(features + base);
    float4 r0 = *(const float4*)(residuals + base);
    float4 r1 = *(const float4*)(residuals + res_stride + base);

    float4 v;
    v.x = fmaxf(f.x + r0.x + r1.x, 0.f);
    v.y = fmaxf(f.y + r0.y + r1.y, 0.f);
    v.z = fmaxf(f.z + r0.z + r1.z, 0.f);
    v.w = fmaxf(f.w + r0.w + r1.w, 0.f);
    *o = v;
}

extern "C" void kernel_launch(void* const* d_in, const int* in_sizes, int n_in,
                              void* d_out, int out_size)
{
    const float* features  = (const float*)d_in[0];
    const float* residuals = (const float*)d_in[1];
    const void*  mol_slice = d_in[2];
    float* out = (float*)d_out;

    dense_block_end_kernel<<<BATCH * MAX_ATOM, THREADS>>>(
        features, residuals, mol_slice, out);
}

// round 3
// speedup vs baseline: 1.0136x; 1.0136x over previous
#include <cuda_runtime.h>
#include <cstdint>

// out = relu( row_mask ? (features + residuals[0] + residuals[1]) : 0 )
// features:  (256, 128, 1024) f32
// residuals: (2, 256, 128, 1024) f32
// mol_slice: (256, 2) int64 OR int32 (runtime-detected)
//
// 4 consecutive rows per block (all in the same batch: 128 % 4 == 0), 256
// threads, one float4 column slot per thread. Unrolled over rows so up to 12
// independent LDG.128 are in flight per thread. Masked rows: zero store only.

#define BATCH 256
#define MAX_ATOM 128
#define N_FEAT 1024
#define THREADS 256        // N_FEAT / 4
#define ROWS_PER_BLK 4

__device__ __forceinline__ void stcs4(float4* p, float4 v) {
    asm volatile("st.global.cs.v4.f32 [%0], {%1,%2,%3,%4};"
                 :: "l"(p), "f"(v.x), "f"(v.y), "f"(v.z), "f"(v.w) : "memory");
}

__global__ __launch_bounds__(THREADS)
void dense_block_end_kernel(const float* __restrict__ features,
                            const float* __restrict__ residuals,
                            const void*  __restrict__ mol_slice,
                            float* __restrict__ out)
{
    const int row0 = blockIdx.x * ROWS_PER_BLK;        // first row of this block
    const int b    = row0 >> 7;                        // / MAX_ATOM (4 | 128)
    const int a0   = row0 & (MAX_ATOM - 1);            // first atom index

    // mol_slice dtype sniff:
    //   int32: [M0, 1024, M1, 1024, ...] -> word[1] == 1024
    //   int64: [M0, 0, 1024, 0, ...]     -> word[1] == 0 (hi word, M <= 128)
    const int* ms32 = (const int*)mol_slice;
    int n_atoms;
    if (ms32[1] == N_FEAT) {
        n_atoms = ms32[2 * b];
    } else {
        n_atoms = (int)((const long long*)mol_slice)[2 * b];
    }

    const size_t res_stride = (size_t)BATCH * MAX_ATOM * N_FEAT;
    const size_t base0 = (size_t)row0 * N_FEAT + threadIdx.x * 4;

    // Front-batch the loads: gather all active rows' data first (independent
    // LDGs), then compute + store.
    float4 f[ROWS_PER_BLK], r0[ROWS_PER_BLK], r1[ROWS_PER_BLK];
    bool act[ROWS_PER_BLK];

    #pragma unroll
    for (int i = 0; i < ROWS_PER_BLK; i++) {
        act[i] = (a0 + i) < n_atoms;
        const size_t base = base0 + (size_t)i * N_FEAT;
        if (act[i]) {
            f[i]  = __ldg((const float4*)(features + base));
            r0[i] = __ldg((const float4*)(residuals + base));
            r1[i] = __ldg((const float4*)(residuals + res_stride + base));
        }
    }

    #pragma unroll
    for (int i = 0; i < ROWS_PER_BLK; i++) {
        const size_t base = base0 + (size_t)i * N_FEAT;
        float4 v = make_float4(0.f, 0.f, 0.f, 0.f);
        if (act[i]) {
            v.x = fmaxf(f[i].x + r0[i].x + r1[i].x, 0.f);
            v.y = fmaxf(f[i].y + r0[i].y + r1[i].y, 0.f);
            v.z = fmaxf(f[i].z + r0[i].z + r1[i].z, 0.f);
            v.w = fmaxf(f[i].w + r0[i].w + r1[i].w, 0.f);
        }
        stcs4((float4*)(out + base), v);
    }
}

extern "C" void kernel_launch(void* const* d_in, const int* in_sizes, int n_in,
                              void* d_out, int out_size)
{
    const float* features  = (const float*)d_in[0];
    const float* residuals = (const float*)d_in[1];
    const void*  mol_slice = d_in[2];
    float* out = (float*)d_out;

    dense_block_end_kernel<<<(BATCH * MAX_ATOM) / ROWS_PER_BLK, THREADS>>>(
        features, residuals, mol_slice, out);
}